// round 4
// baseline (speedup 1.0000x reference)
#include <cuda_runtime.h>
#include <math.h>

#define BB   128
#define HH   4
#define NN   8192
#define DD   64
#define NT   16          // tiles per batch
#define TILE 512         // rows per tile (NT*TILE == NN)
#define EPSF 1e-8f
#define NEGINF (-3.0e38f)

// Scratch: per-(b, tile, head8) top-8 candidates: {value, idx-as-float-bits}
__device__ float2 g_cand[BB * NT * 8 * 8];

// ---------------------------------------------------------------------------
// packed fp32x2 helpers (sm_103a FFMA2 path)
// ---------------------------------------------------------------------------
__device__ __forceinline__ unsigned long long fma2(unsigned long long a,
                                                   unsigned long long b,
                                                   unsigned long long c) {
    unsigned long long d;
    asm("fma.rn.f32x2 %0, %1, %2, %3;" : "=l"(d) : "l"(a), "l"(b), "l"(c));
    return d;
}
__device__ __forceinline__ unsigned long long mul2(unsigned long long a,
                                                   unsigned long long b) {
    unsigned long long d;
    asm("mul.rn.f32x2 %0, %1, %2;" : "=l"(d) : "l"(a), "l"(b));
    return d;
}
__device__ __forceinline__ float hadd2(unsigned long long a) {
    float lo, hi;
    asm("mov.b64 {%0, %1}, %2;" : "=f"(lo), "=f"(hi) : "l"(a));
    return lo + hi;
}
#define FOUR2 0x4080000040800000ULL   // (4.0f, 4.0f)

// ---------------------------------------------------------------------------
// Sorted-descending top-8 insertion (all static register indices)
// ---------------------------------------------------------------------------
__device__ __forceinline__ void insert8(float v, int idx, float tv[8], int ti[8]) {
    if (v <= tv[7]) return;
    tv[7] = v; ti[7] = idx;
#pragma unroll
    for (int s = 7; s > 0; --s) {
        if (tv[s] > tv[s-1]) {
            float t = tv[s]; tv[s] = tv[s-1]; tv[s-1] = t;
            int t2 = ti[s]; ti[s] = ti[s-1]; ti[s-1] = t2;
        }
    }
}

__device__ __forceinline__ void cswap(float& a, int& ai, float& b, int& bi) {
    if (b > a) { float t = a; a = b; b = t; int t2 = ai; ai = bi; bi = t2; }
}

// Butterfly merge of per-lane sorted top-8 lists across the warp.
__device__ __forceinline__ void warp_merge8(float tv[8], int ti[8]) {
#pragma unroll
    for (int off = 16; off >= 1; off >>= 1) {
        float ov[8]; int oi[8];
#pragma unroll
        for (int k = 0; k < 8; ++k) {
            ov[k] = __shfl_xor_sync(0xffffffffu, tv[k], off);
            oi[k] = __shfl_xor_sync(0xffffffffu, ti[k], off);
        }
        float nv[8]; int ni[8];
#pragma unroll
        for (int k = 0; k < 8; ++k) {
            if (tv[k] >= ov[7-k]) { nv[k] = tv[k];   ni[k] = ti[k];   }
            else                  { nv[k] = ov[7-k]; ni[k] = oi[7-k]; }
        }
        cswap(nv[0],ni[0],nv[4],ni[4]); cswap(nv[1],ni[1],nv[5],ni[5]);
        cswap(nv[2],ni[2],nv[6],ni[6]); cswap(nv[3],ni[3],nv[7],ni[7]);
        cswap(nv[0],ni[0],nv[2],ni[2]); cswap(nv[1],ni[1],nv[3],ni[3]);
        cswap(nv[4],ni[4],nv[6],ni[6]); cswap(nv[5],ni[5],nv[7],ni[7]);
        cswap(nv[0],ni[0],nv[1],ni[1]); cswap(nv[2],ni[2],nv[3],ni[3]);
        cswap(nv[4],ni[4],nv[5],ni[5]); cswap(nv[6],ni[6],nv[7],ni[7]);
#pragma unroll
        for (int k = 0; k < 8; ++k) { tv[k] = nv[k]; ti[k] = ni[k]; }
    }
}

// ---------------------------------------------------------------------------
// K1: single streaming pass over memory.
//  Per warp-iteration (4 rows): coalesced load, fused 4x store, stage rows
//  into padded smem, then lane (row=lane>>3, head=lane&7) computes its head's
//  full 64-dim dot with packed FFMA2 (no cross-lane reduction for dots).
// ---------------------------------------------------------------------------
__global__ __launch_bounds__(256)
void k1_stream(const float* __restrict__ mem,
               const float* __restrict__ rk,
               const float* __restrict__ wk,
               float* __restrict__ new_mem,
               float* __restrict__ o_rw,
               float* __restrict__ o_ww)
{
    __shared__ __align__(16) float s_sim[TILE * 8];        // 16 KB
    __shared__ __align__(16) float s_key[8 * 68];          // padded stride 68
    __shared__ __align__(16) float s_stage[8 * 2 * 4 * 68];// 8 warps x 2 bufs x 4 rows
    __shared__ float s_knorm[8];

    const int b    = blockIdx.y;
    const int tile = blockIdx.x;
    const int tid  = threadIdx.x;
    const int lane = tid & 31;
    const int warp = tid >> 5;          // 8 warps
    const int j    = lane & 7;          // head index AND dim-slice index
    const int rsub = lane >> 3;         // row within 4-row group

    // Zero the dense weight slices owned by this (b, tile) — vectorized
    {
        float4 z4 = make_float4(0.f, 0.f, 0.f, 0.f);
        for (int v = tid; v < 512; v += 256) {             // 2048 floats each
            const int h   = v >> 7;
            const int off = (v & 127) * 4;
            const size_t o = (((size_t)b * HH + h) * NN + (size_t)tile * TILE + off) / 4;
            ((float4*)o_rw)[o] = z4;
            ((float4*)o_ww)[o] = z4;
        }
    }

    // Key norms (8 keys, one thread each) — straight from global
    if (tid < 8) {
        const float* kp = (tid < 4) ? rk + ((size_t)b * HH + tid) * DD
                                    : wk + ((size_t)b * HH + (tid - 4)) * DD;
        float s = 0.f;
        for (int d = 0; d < DD; ++d) s += kp[d] * kp[d];
        s_knorm[tid] = fmaxf(sqrtf(s), EPSF);
    }

    // Keys into padded shared: s_key[h*68 + d]
    for (int i = tid; i < 8 * DD; i += 256) {
        const int h = i >> 6, d = i & 63;
        const float* kp = (h < 4) ? rk + ((size_t)b * HH + h) * DD
                                  : wk + ((size_t)b * HH + (h - 4)) * DD;
        s_key[h * 68 + d] = kp[d];
    }
    __syncthreads();

    const float knj = s_knorm[j];
    const ulonglong2* keyrow = (const ulonglong2*)(s_key + j * 68);

    const float* mb = mem     + ((size_t)b * NN + (size_t)tile * TILE) * DD;
    float*       ob = new_mem + ((size_t)b * NN + (size_t)tile * TILE) * DD;
    float* stbase = s_stage + warp * (2 * 4 * 68);

    int pbuf = 0;
    for (int it = warp * 4; it < TILE; it += 32, pbuf ^= 1) {
        const int r = it + rsub;

        // coalesced 32-B slice load (lane l <-> byte offset 32*l)
        const ulonglong2* p = (const ulonglong2*)(mb + (size_t)r * DD + j * 8);
        ulonglong2 a0 = p[0], a1 = p[1];

        // fused new_memory = 4*memory (coalesced store)
        ulonglong2 q0, q1;
        q0.x = mul2(a0.x, FOUR2); q0.y = mul2(a0.y, FOUR2);
        q1.x = mul2(a1.x, FOUR2); q1.y = mul2(a1.y, FOUR2);
        ulonglong2* qp = (ulonglong2*)(ob + (size_t)r * DD + j * 8);
        qp[0] = q0; qp[1] = q1;

        // stage row slice into padded smem
        float* st = stbase + pbuf * (4 * 68) + rsub * 68 + j * 8;
        ((ulonglong2*)st)[0] = a0;
        ((ulonglong2*)st)[1] = a1;

        // row-norm partial (packed) + 3-shuffle reduce over the 8 row lanes
        unsigned long long na = mul2(a0.x, a0.x);
        na = fma2(a0.y, a0.y, na);
        na = fma2(a1.x, a1.x, na);
        na = fma2(a1.y, a1.y, na);
        float nr = hadd2(na);
        nr += __shfl_xor_sync(0xffffffffu, nr, 1);
        nr += __shfl_xor_sync(0xffffffffu, nr, 2);
        nr += __shfl_xor_sync(0xffffffffu, nr, 4);

        __syncwarp();

        // full 64-dim dot for head j of row rsub, packed FFMA2, no shuffles
        const ulonglong2* row2 = (const ulonglong2*)(stbase + pbuf * (4 * 68) + rsub * 68);
        unsigned long long acc = 0ULL;
#pragma unroll
        for (int t = 0; t < 16; ++t) {
            ulonglong2 rv = row2[t];
            ulonglong2 kv = keyrow[t];
            acc = fma2(rv.x, kv.x, acc);
            acc = fma2(rv.y, kv.y, acc);
        }
        const float dj = hadd2(acc);

        const float mn = fmaxf(sqrtf(nr), EPSF);
        s_sim[r * 8 + j] = 10.f * __fdividef(dj, knj * mn + EPSF);
    }
    __syncthreads();

    // Per-head top-8 within this tile: warp w handles head w
    float tv[8]; int ti[8];
#pragma unroll
    for (int k = 0; k < 8; ++k) { tv[k] = NEGINF; ti[k] = 0; }
    for (int r = lane; r < TILE; r += 32)
        insert8(s_sim[r * 8 + warp], tile * TILE + r, tv, ti);
    warp_merge8(tv, ti);

    if (lane == 0) {
        float2* o = g_cand + (((b * NT + tile) * 8) + warp) * 8;
#pragma unroll
        for (int k = 0; k < 8; ++k) o[k] = make_float2(tv[k], __int_as_float(ti[k]));
    }
}

// ---------------------------------------------------------------------------
// K2: per (b, head8) warp — merge tile candidates into exact top-8, softmax,
// scatter dense weights, apply read gather / write fix-ups.
// ---------------------------------------------------------------------------
__global__ __launch_bounds__(256)
void k2_apply(const float* __restrict__ mem,
              const float* __restrict__ wv,
              const float* __restrict__ er,
              float* __restrict__ o_rc,
              float* __restrict__ o_rw,
              float* __restrict__ new_mem,
              float* __restrict__ o_ww)
{
    __shared__ float s_rc[4][DD];

    const int b    = blockIdx.x;
    const int tid  = threadIdx.x;
    const int lane = tid & 31;
    const int h8   = tid >> 5;          // 8 warps -> 8 (b, head8) rows

    float tv[8]; int ti[8];
#pragma unroll
    for (int k = 0; k < 8; ++k) { tv[k] = NEGINF; ti[k] = 0; }

    for (int e = lane; e < NT * 8; e += 32) {
        const int tile = e >> 3, k = e & 7;
        const float2 c = g_cand[(((b * NT + tile) * 8) + h8) * 8 + k];
        insert8(c.x, __float_as_int(c.y), tv, ti);
    }
    warp_merge8(tv, ti);   // every lane now holds the row's exact top-8

    // softmax over the 8 survivors
    float w[8]; float s = 0.f;
#pragma unroll
    for (int k = 0; k < 8; ++k) { w[k] = expf(tv[k] - tv[0]); s += w[k]; }
    const float inv = __fdividef(1.f, s);
#pragma unroll
    for (int k = 0; k < 8; ++k) w[k] *= inv;

    // scatter dense weights
    if (lane == 0) {
        float* dense = (h8 < 4) ? o_rw + ((size_t)b * HH + h8) * NN
                                : o_ww + ((size_t)b * HH + (h8 - 4)) * NN;
#pragma unroll
        for (int k = 0; k < 8; ++k) dense[ti[k]] = w[k];
    }

    const int d = lane * 2;
    if (h8 < 4) {
        float ax = 0.f, ay = 0.f;
#pragma unroll
        for (int k = 0; k < 8; ++k) {
            const float2 m2 = *(const float2*)(mem + ((size_t)b * NN + ti[k]) * DD + d);
            ax += w[k] * m2.x;
            ay += w[k] * m2.y;
        }
        s_rc[h8][d]     = 0.25f * ax;
        s_rc[h8][d + 1] = 0.25f * ay;
    } else {
        const int h = h8 - 4;
        const float2 e2 = *(const float2*)(er + ((size_t)b * HH + h) * DD + d);
        const float2 v2 = *(const float2*)(wv + ((size_t)b * HH + h) * DD + d);
#pragma unroll
        for (int k = 0; k < 8; ++k) {
            const float2 m2 = *(const float2*)(mem + ((size_t)b * NN + ti[k]) * DD + d);
            float* dst = new_mem + ((size_t)b * NN + ti[k]) * DD + d;
            atomicAdd(dst,     w[k] * (v2.x - m2.x * e2.x));
            atomicAdd(dst + 1, w[k] * (v2.y - m2.y * e2.y));
        }
    }
    __syncthreads();
    if (tid < DD)
        o_rc[(size_t)b * DD + tid] = s_rc[0][tid] + s_rc[1][tid] + s_rc[2][tid] + s_rc[3][tid];
}

// ---------------------------------------------------------------------------
extern "C" void kernel_launch(void* const* d_in, const int* in_sizes, int n_in,
                              void* d_out, int out_size)
{
    const float* mem = (const float*)d_in[0];
    const float* rk  = (const float*)d_in[1];
    const float* wk  = (const float*)d_in[2];
    const float* wv  = (const float*)d_in[3];
    const float* er  = (const float*)d_in[4];

    float* out  = (float*)d_out;
    float* o_rc = out;                                   // (B, D)
    float* o_rw = o_rc + (size_t)BB * DD;                // (B, H, N)
    float* o_nm = o_rw + (size_t)BB * HH * NN;           // (B, N, D)
    float* o_ww = o_nm + (size_t)BB * NN * DD;           // (B, H, N)

    k1_stream<<<dim3(NT, BB), 256>>>(mem, rk, wk, o_nm, o_rw, o_ww);
    k2_apply<<<BB, 256>>>(mem, wv, er, o_rc, o_rw, o_nm, o_ww);
}